// round 8
// baseline (speedup 1.0000x reference)
#include <cuda_runtime.h>
#include <cuda_fp16.h>
#include <cstdint>
#include <cstddef>

// ScalarWaveletRecombiner: out[n,o] = W2[o]·silu(W1[o]·x[n] + b1[o]) + b2[o]
// x:[NC,64] W1:[32,128,64] b1:[32,128] W2:[32,128] b2:[32] -> out:[NC,32]
//
// v4: fp16 mma.sync.m16n8k16 (11-bit significand == tf32), fp32 accumulate.
//   grid (NC/256, 8); 512 threads = 16 warps (m32 x n64); 4 MLPs/CTA.
//   smem layout [k-chunk(8 fp16)][row][16B]: 16B-stride rows -> conflict-free
//   ldmatrix.x4 with zero swizzle math. A fragments hoisted across all 4 MLPs.
//   Epilogue: silu via 1x tanh.approx + W2 reduction, one final sync.

#define KDIM 64
#define HDIM 128
#define ODIM 32
#define OPB 4
#define ROWS 256
#define THREADS 512

// smem layout (bytes)
#define XS_OFF    0         // fp16 x  [8 kc][256 rows][16B] = 32768
#define WS_OFF    32768     // fp16 W1 [8 kc][512 rows][16B] = 65536
#define BW_OFF    98304     // float2 (0.5*b1, w2) [4][128]  = 4096
#define PART_OFF  102400    // float [8][256]                = 8192
#define SMEM_BYTES 110592

__device__ __forceinline__ unsigned pack_f16x2(float lo, float hi) {
    unsigned r;
    asm("cvt.rn.f16x2.f32 %0, %2, %1;" : "=r"(r) : "f"(lo), "f"(hi));
    return r;
}

__device__ __forceinline__ uint32_t smem_u32(const void* p) {
    uint32_t a;
    asm("{ .reg .u64 t; cvta.to.shared.u64 t, %1; cvt.u32.u64 %0, t; }" : "=r"(a) : "l"(p));
    return a;
}

__device__ __forceinline__ void ldsm4(uint32_t addr, unsigned* r) {
    asm volatile("ldmatrix.sync.aligned.m8n8.x4.shared.b16 {%0,%1,%2,%3}, [%4];"
                 : "=r"(r[0]), "=r"(r[1]), "=r"(r[2]), "=r"(r[3]) : "r"(addr));
}

__device__ __forceinline__ void mma_f16(float* c, const unsigned* a, unsigned b0, unsigned b1) {
    asm volatile(
        "mma.sync.aligned.m16n8k16.row.col.f32.f16.f16.f32 "
        "{%0,%1,%2,%3},{%4,%5,%6,%7},{%8,%9},{%0,%1,%2,%3};"
        : "+f"(c[0]), "+f"(c[1]), "+f"(c[2]), "+f"(c[3])
        : "r"(a[0]), "r"(a[1]), "r"(a[2]), "r"(a[3]), "r"(b0), "r"(b1));
}

__device__ __forceinline__ float tanh_ap(float x) {
    float t;
    asm("tanh.approx.f32 %0, %1;" : "=f"(t) : "f"(x));
    return t;
}

__global__ __launch_bounds__(THREADS, 1)
void swr_kernel(const float* __restrict__ x, const float* __restrict__ W1,
                const float* __restrict__ b1, const float* __restrict__ W2,
                const float* __restrict__ b2, float* __restrict__ out)
{
    extern __shared__ char sm[];
    float2* bw   = (float2*)(sm + BW_OFF);
    float*  part = (float*)(sm + PART_OFF);

    const int tid = threadIdx.x;
    const int R0  = blockIdx.x * ROWS;
    const int o0  = blockIdx.y * OPB;

    // ---- stage x as fp16: chunk kc holds k in [8kc, 8kc+8), row stride 16B ----
    // kc-major thread mapping: STS conflict-free (consecutive threads -> rows)
    #pragma unroll
    for (int i = 0; i < 4; i++) {
        int idx = tid + i * THREADS;             // 2048 chunks
        int kc = idx >> 8, r = idx & 255;
        const float* p = x + (size_t)(R0 + r) * KDIM + kc * 8;
        float4 v0 = *(const float4*)p;
        float4 v1 = *(const float4*)(p + 4);
        uint4 u;
        u.x = pack_f16x2(v0.x, v0.y); u.y = pack_f16x2(v0.z, v0.w);
        u.z = pack_f16x2(v1.x, v1.y); u.w = pack_f16x2(v1.z, v1.w);
        *(uint4*)(sm + XS_OFF + kc * 4096 + r * 16) = u;
    }

    // ---- stage W1 as fp16: [8 kc][512 rows (4 o x 128 h)][16B] ----
    #pragma unroll
    for (int i = 0; i < 8; i++) {
        int idx = tid + i * THREADS;             // 4096 chunks
        int kc = idx >> 9, nr = idx & 511;
        int ol = nr >> 7, h = nr & 127;
        const float* p = W1 + ((size_t)(o0 + ol) * HDIM + h) * KDIM + kc * 8;
        float4 v0 = *(const float4*)p;
        float4 v1 = *(const float4*)(p + 4);
        uint4 u;
        u.x = pack_f16x2(v0.x, v0.y); u.y = pack_f16x2(v0.z, v0.w);
        u.z = pack_f16x2(v1.x, v1.y); u.w = pack_f16x2(v1.z, v1.w);
        *(uint4*)(sm + WS_OFF + kc * 8192 + nr * 16) = u;
    }

    // ---- stage (0.5*b1, w2) pairs ----
    {
        int ol = tid >> 7, h = tid & 127;
        bw[tid] = make_float2(0.5f * b1[(o0 + ol) * HDIM + h], W2[(o0 + ol) * HDIM + h]);
    }
    __syncthreads();

    const int w    = tid >> 5;
    const int lane = tid & 31;
    const int rg   = w >> 1;                 // row-group (32 rows)
    const int cg   = w & 1;                  // col-group (64 h)
    const int rw   = rg * 32;
    const int hb   = cg * 64;
    const int gid  = lane >> 2;
    const int tig  = lane & 3;

    const uint32_t smb = smem_u32(sm);

    // A ldmatrix lane address: lanes 0-15 -> rows (rw + L&15) k-lo chunk,
    // lanes 16-31 -> same rows k-hi chunk (chunk stride 4096)
    const uint32_t pA0 = smb + XS_OFF + (uint32_t)(lane >> 4) * 4096
                       + (uint32_t)(rw + (lane & 15)) * 16;
    const uint32_t pA1 = pA0 + 16 * 16;      // rows rw+16..rw+31

    // B ldmatrix lane address: m0/m1 = n-rows 0-7 (k-lo/k-hi), m2/m3 = n-rows 8-15
    const uint32_t pB = smb + WS_OFF + (uint32_t)((lane >> 3) & 1) * 8192
                      + (uint32_t)(hb + ((lane >> 4) * 8) + (lane & 7)) * 16;

    // ---- hoist all A fragments (shared across the 4 MLPs) ----
    unsigned a[4][2][4];
    #pragma unroll
    for (int kk = 0; kk < 4; ++kk) {
        ldsm4(pA0 + (uint32_t)kk * 8192, a[kk][0]);
        ldsm4(pA1 + (uint32_t)kk * 8192, a[kk][1]);
    }

    #pragma unroll 1
    for (int ol = 0; ol < OPB; ++ol) {
        float c[2][8][4];
        #pragma unroll
        for (int n = 0; n < 8; ++n)
            #pragma unroll
            for (int t = 0; t < 2; ++t) {
                c[t][n][0] = 0.f; c[t][n][1] = 0.f; c[t][n][2] = 0.f; c[t][n][3] = 0.f;
            }

        const uint32_t pBo = pB + (uint32_t)ol * 2048;   // ol*128 rows * 16B

        #pragma unroll
        for (int kk = 0; kk < 4; ++kk) {
            const uint32_t pBk = pBo + (uint32_t)kk * 16384;
            #pragma unroll
            for (int p = 0; p < 4; ++p) {
                unsigned b[4];   // (b0,b1) for n-tile 2p ; (b0,b1) for n-tile 2p+1
                ldsm4(pBk + (uint32_t)p * 256, b);
                mma_f16(c[0][2 * p],     a[kk][0], b[0], b[1]);
                mma_f16(c[0][2 * p + 1], a[kk][0], b[2], b[3]);
                mma_f16(c[1][2 * p],     a[kk][1], b[0], b[1]);
                mma_f16(c[1][2 * p + 1], a[kk][1], b[2], b[3]);
            }
        }

        // ---- fused epilogue: silu (tanh.approx) + W2 reduction ----
        float acc[2][2] = {{0.f, 0.f}, {0.f, 0.f}};
        const float4* bwp = (const float4*)(bw + ol * HDIM + hb + tig * 2);
        #pragma unroll
        for (int n = 0; n < 8; ++n) {
            float4 q = bwp[n * 4];   // (0.5*b1[h0], w2[h0], 0.5*b1[h1], w2[h1])
            #pragma unroll
            for (int t = 0; t < 2; ++t) {
                float h00 = fmaf(c[t][n][0], 0.5f, q.x);
                float h01 = fmaf(c[t][n][1], 0.5f, q.z);
                float h10 = fmaf(c[t][n][2], 0.5f, q.x);
                float h11 = fmaf(c[t][n][3], 0.5f, q.z);
                acc[t][0] = fmaf(fmaf(h00, tanh_ap(h00), h00), q.y, acc[t][0]);
                acc[t][0] = fmaf(fmaf(h01, tanh_ap(h01), h01), q.w, acc[t][0]);
                acc[t][1] = fmaf(fmaf(h10, tanh_ap(h10), h10), q.y, acc[t][1]);
                acc[t][1] = fmaf(fmaf(h11, tanh_ap(h11), h11), q.w, acc[t][1]);
            }
        }

        #pragma unroll
        for (int t = 0; t < 2; ++t)
            #pragma unroll
            for (int r = 0; r < 2; ++r) {
                float v = acc[t][r];
                v += __shfl_xor_sync(0xffffffffu, v, 1);
                v += __shfl_xor_sync(0xffffffffu, v, 2);
                if (tig == 0)
                    part[(ol * 2 + cg) * 256 + rw + t * 16 + r * 8 + gid] = v;
            }
    }

    __syncthreads();

    // ---- combine cg partials, add b2, coalesced float4 store ----
    if (tid < 256) {
        float4 o;
        float* po = (float*)&o;
        #pragma unroll
        for (int ol = 0; ol < OPB; ++ol)
            po[ol] = part[(ol * 2) * 256 + tid] + part[(ol * 2 + 1) * 256 + tid]
                   + __ldg(b2 + o0 + ol);
        *(float4*)(out + (size_t)(R0 + tid) * ODIM + o0) = o;
    }
}

extern "C" void kernel_launch(void* const* d_in, const int* in_sizes, int n_in,
                              void* d_out, int out_size)
{
    const float* x  = (const float*)d_in[0];  // [NC, 64]
    const float* W1 = (const float*)d_in[1];  // [32, 128, 64]
    const float* b1 = (const float*)d_in[2];  // [32, 128]
    const float* W2 = (const float*)d_in[3];  // [32, 128]
    const float* b2 = (const float*)d_in[4];  // [32]
    float* out = (float*)d_out;               // [NC, 32]

    const int NC = in_sizes[0] / KDIM;        // 131072

    cudaFuncSetAttribute(swr_kernel, cudaFuncAttributeMaxDynamicSharedMemorySize, SMEM_BYTES);

    dim3 grid(NC / ROWS, ODIM / OPB);         // (512, 8)
    swr_kernel<<<grid, THREADS, SMEM_BYTES>>>(x, W1, b1, W2, b2, out);
}